// round 1
// baseline (speedup 1.0000x reference)
#include <cuda_runtime.h>
#include <math.h>

// ---------------- problem constants ----------------
#define S_SLOTS 4096
#define N_IN    16384
#define D_DIM   768
#define D3      2304

// ---------------- scratch (device globals; no allocations allowed) ------
__device__ float g_pano_ln[N_IN * D_DIM];
__device__ float g_k      [N_IN * D_DIM];
__device__ float g_v      [N_IN * D_DIM];
__device__ float g_slots  [S_SLOTS * D_DIM];
__device__ float g_tmp    [S_SLOTS * D_DIM];
__device__ float g_q      [S_SLOTS * D_DIM];
__device__ float g_dots   [(size_t)S_SLOTS * N_IN];   // 256 MB
__device__ float g_lsum   [S_SLOTS];
__device__ float g_upd    [S_SLOTS * D_DIM];
__device__ float g_gx     [S_SLOTS * D3];
__device__ float g_gh     [S_SLOTS * D3];
__device__ float g_h      [S_SLOTS * D_DIM];
__device__ float g_t      [S_SLOTS * D_DIM];

// ---------------- reductions ----------------
__device__ __forceinline__ float blk_sum(float v, float* sm) {
    #pragma unroll
    for (int o = 16; o; o >>= 1) v += __shfl_xor_sync(0xffffffffu, v, o);
    int w = threadIdx.x >> 5;
    if ((threadIdx.x & 31) == 0) sm[w] = v;
    __syncthreads();
    if (threadIdx.x < 8) {
        float x = sm[threadIdx.x];
        #pragma unroll
        for (int o = 4; o; o >>= 1) x += __shfl_xor_sync(0xffu, x, o);
        if (threadIdx.x == 0) sm[0] = x;
    }
    __syncthreads();
    float r = sm[0];
    __syncthreads();
    return r;
}

__device__ __forceinline__ float blk_max(float v, float* sm) {
    #pragma unroll
    for (int o = 16; o; o >>= 1) v = fmaxf(v, __shfl_xor_sync(0xffffffffu, v, o));
    int w = threadIdx.x >> 5;
    if ((threadIdx.x & 31) == 0) sm[w] = v;
    __syncthreads();
    if (threadIdx.x < 8) {
        float x = sm[threadIdx.x];
        #pragma unroll
        for (int o = 4; o; o >>= 1) x = fmaxf(x, __shfl_xor_sync(0xffu, x, o));
        if (threadIdx.x == 0) sm[0] = x;
    }
    __syncthreads();
    float r = sm[0];
    __syncthreads();
    return r;
}

// ---------------- elementwise kernels ----------------
__global__ void copy_kernel(const float* __restrict__ in, float* __restrict__ out, int n) {
    int i = blockIdx.x * 256 + threadIdx.x;
    if (i < n) out[i] = in[i];
}

// One block per row; D = 768, 256 threads, 3 elements per thread.
__global__ void __launch_bounds__(256) ln_kernel(
    const float* __restrict__ x, const float* __restrict__ g,
    const float* __restrict__ be, float* __restrict__ y)
{
    __shared__ float sm[8];
    int row = blockIdx.x;
    const float* xr = x + (size_t)row * D_DIM;
    int t = threadIdx.x;
    float v0 = xr[t], v1 = xr[t + 256], v2 = xr[t + 512];
    float s = blk_sum(v0 + v1 + v2, sm);
    float mean = s * (1.0f / 768.0f);
    float d0 = v0 - mean, d1 = v1 - mean, d2 = v2 - mean;
    float ss = blk_sum(d0 * d0 + d1 * d1 + d2 * d2, sm);
    float inv = rsqrtf(ss * (1.0f / 768.0f) + 1e-5f);
    float* yr = y + (size_t)row * D_DIM;
    yr[t]       = d0 * inv * g[t]       + be[t];
    yr[t + 256] = d1 * inv * g[t + 256] + be[t + 256];
    yr[t + 512] = d2 * inv * g[t + 512] + be[t + 512];
}

// One block per row of 16384: max, then unnormalized exp in-place, sum -> lsum.
__global__ void __launch_bounds__(256) softmax_kernel(
    float* __restrict__ dots, float* __restrict__ lsum)
{
    __shared__ float sm[8];
    int row = blockIdx.x;
    float4* p = (float4*)(dots + (size_t)row * N_IN);
    float4 buf[16];
    float m = -1e30f;
    #pragma unroll
    for (int i = 0; i < 16; i++) {
        buf[i] = p[threadIdx.x + i * 256];
        m = fmaxf(m, fmaxf(fmaxf(buf[i].x, buf[i].y), fmaxf(buf[i].z, buf[i].w)));
    }
    m = blk_max(m, sm);
    float s = 0.0f;
    #pragma unroll
    for (int i = 0; i < 16; i++) {
        float4 e;
        e.x = expf(buf[i].x - m); e.y = expf(buf[i].y - m);
        e.z = expf(buf[i].z - m); e.w = expf(buf[i].w - m);
        s += (e.x + e.y) + (e.z + e.w);
        p[threadIdx.x + i * 256] = e;
    }
    s = blk_sum(s, sm);
    if (threadIdx.x == 0) lsum[row] = s;
}

__global__ void rowscale_kernel(float* __restrict__ u, const float* __restrict__ l) {
    int idx = blockIdx.x * 256 + threadIdx.x;    // over S*D
    int row = idx / D_DIM;
    u[idx] = u[idx] / l[row];
}

__global__ void gru_kernel(const float* __restrict__ gx, const float* __restrict__ gh,
                           const float* __restrict__ sp, float* __restrict__ h)
{
    int idx = blockIdx.x * 256 + threadIdx.x;    // over S*D
    int i = idx / D_DIM, d = idx - i * D_DIM;
    size_t b3 = (size_t)i * D3;
    float xr = gx[b3 + d], xz = gx[b3 + D_DIM + d], xn = gx[b3 + 2 * D_DIM + d];
    float hr = gh[b3 + d], hz = gh[b3 + D_DIM + d], hn = gh[b3 + 2 * D_DIM + d];
    float r = 1.0f / (1.0f + expf(-(xr + hr)));
    float z = 1.0f / (1.0f + expf(-(xz + hz)));
    float n = tanhf(xn + r * hn);
    h[idx] = (1.0f - z) * n + z * sp[idx];
}

// ---------------- GEMMs (fp32 SIMT, 64x64x16 tiles, 4x4 micro) ----------------
// C[i,j] = alpha * sum_k A[i,k]*B[j,k] (+bias[j]) (RELU) (+add[i,j])
template <bool RELU>
__global__ void __launch_bounds__(256) gemm_nt_kernel(
    const float* __restrict__ A, const float* __restrict__ B,
    const float* __restrict__ bias, const float* __restrict__ addsrc,
    float* __restrict__ C, int M, int N, int K, float alpha)
{
    __shared__ float As[16][68];
    __shared__ float Bs[16][68];
    int tid = threadIdx.x;
    int tx = tid & 15, ty = tid >> 4;
    int row0 = blockIdx.y * 64, col0 = blockIdx.x * 64;
    int lr = tid >> 2;            // 0..63
    int lk = (tid & 3) * 4;       // 0,4,8,12

    const float* Aptr = A + (size_t)(row0 + lr) * K + lk;
    const float* Bptr = B + (size_t)(col0 + lr) * K + lk;
    float acc[4][4] = {};

    for (int k0 = 0; k0 < K; k0 += 16) {
        float4 a = *(const float4*)(Aptr + k0);
        float4 b = *(const float4*)(Bptr + k0);
        As[lk + 0][lr] = a.x; As[lk + 1][lr] = a.y; As[lk + 2][lr] = a.z; As[lk + 3][lr] = a.w;
        Bs[lk + 0][lr] = b.x; Bs[lk + 1][lr] = b.y; Bs[lk + 2][lr] = b.z; Bs[lk + 3][lr] = b.w;
        __syncthreads();
        #pragma unroll
        for (int k = 0; k < 16; k++) {
            float4 av = *(const float4*)&As[k][ty * 4];
            float4 bv = *(const float4*)&Bs[k][tx * 4];
            float ar[4] = {av.x, av.y, av.z, av.w};
            float br[4] = {bv.x, bv.y, bv.z, bv.w};
            #pragma unroll
            for (int r = 0; r < 4; r++)
                #pragma unroll
                for (int c = 0; c < 4; c++)
                    acc[r][c] += ar[r] * br[c];
        }
        __syncthreads();
    }

    float4 bv4 = make_float4(0.f, 0.f, 0.f, 0.f);
    if (bias) bv4 = *(const float4*)&bias[col0 + tx * 4];
    #pragma unroll
    for (int r = 0; r < 4; r++) {
        size_t base = (size_t)(row0 + ty * 4 + r) * N + col0 + tx * 4;
        float4 o;
        o.x = acc[r][0] * alpha + bv4.x;
        o.y = acc[r][1] * alpha + bv4.y;
        o.z = acc[r][2] * alpha + bv4.z;
        o.w = acc[r][3] * alpha + bv4.w;
        if (RELU) {
            o.x = fmaxf(o.x, 0.f); o.y = fmaxf(o.y, 0.f);
            o.z = fmaxf(o.z, 0.f); o.w = fmaxf(o.w, 0.f);
        }
        if (addsrc) {
            float4 ad = *(const float4*)&addsrc[base];
            o.x += ad.x; o.y += ad.y; o.z += ad.z; o.w += ad.w;
        }
        *(float4*)&C[base] = o;
    }
}

// C[i,j] = sum_k A[i,k]*B[k,j]   (A row-major [M,K], B row-major [K,N])
__global__ void __launch_bounds__(256) gemm_nn_kernel(
    const float* __restrict__ A, const float* __restrict__ B,
    float* __restrict__ C, int M, int N, int K)
{
    __shared__ float As[16][68];
    __shared__ float Bs[16][68];
    int tid = threadIdx.x;
    int tx = tid & 15, ty = tid >> 4;
    int row0 = blockIdx.y * 64, col0 = blockIdx.x * 64;
    int lr = tid >> 2, lk = (tid & 3) * 4;   // A load
    int bk = tid >> 4, bj = (tid & 15) * 4;  // B load

    const float* Aptr = A + (size_t)(row0 + lr) * K + lk;
    float acc[4][4] = {};

    for (int k0 = 0; k0 < K; k0 += 16) {
        float4 a = *(const float4*)(Aptr + k0);
        As[lk + 0][lr] = a.x; As[lk + 1][lr] = a.y; As[lk + 2][lr] = a.z; As[lk + 3][lr] = a.w;
        float4 b = *(const float4*)(B + (size_t)(k0 + bk) * N + col0 + bj);
        *(float4*)&Bs[bk][bj] = b;
        __syncthreads();
        #pragma unroll
        for (int k = 0; k < 16; k++) {
            float4 av = *(const float4*)&As[k][ty * 4];
            float4 bv = *(const float4*)&Bs[k][tx * 4];
            float ar[4] = {av.x, av.y, av.z, av.w};
            float br[4] = {bv.x, bv.y, bv.z, bv.w};
            #pragma unroll
            for (int r = 0; r < 4; r++)
                #pragma unroll
                for (int c = 0; c < 4; c++)
                    acc[r][c] += ar[r] * br[c];
        }
        __syncthreads();
    }
    #pragma unroll
    for (int r = 0; r < 4; r++) {
        size_t base = (size_t)(row0 + ty * 4 + r) * N + col0 + tx * 4;
        float4 o = make_float4(acc[r][0], acc[r][1], acc[r][2], acc[r][3]);
        *(float4*)&C[base] = o;
    }
}

// ---------------- host launch ----------------
extern "C" void kernel_launch(void* const* d_in, const int* in_sizes, int n_in,
                              void* d_out, int out_size)
{
    (void)in_sizes; (void)n_in; (void)out_size;
    const float* cand  = (const float*)d_in[0];
    const float* pano  = (const float*)d_in[1];
    const float* Wq    = (const float*)d_in[2];
    const float* bq    = (const float*)d_in[3];
    const float* Wk    = (const float*)d_in[4];
    const float* bk    = (const float*)d_in[5];
    const float* Wv    = (const float*)d_in[6];
    const float* bv    = (const float*)d_in[7];
    const float* Wih   = (const float*)d_in[8];
    const float* bih   = (const float*)d_in[9];
    const float* Whh   = (const float*)d_in[10];
    const float* bhh   = (const float*)d_in[11];
    const float* W1    = (const float*)d_in[12];
    const float* b1    = (const float*)d_in[13];
    const float* W2    = (const float*)d_in[14];
    const float* b2    = (const float*)d_in[15];
    const float* gin   = (const float*)d_in[16];
    const float* bein  = (const float*)d_in[17];
    const float* gsl   = (const float*)d_in[18];
    const float* besl  = (const float*)d_in[19];
    const float* gff   = (const float*)d_in[20];
    const float* beff  = (const float*)d_in[21];

    float *pln, *pk, *pv, *pslots, *ptmp, *pq, *pdots, *pl, *pupd, *pgx, *pgh, *ph, *pt;
    cudaGetSymbolAddress((void**)&pln,   g_pano_ln);
    cudaGetSymbolAddress((void**)&pk,    g_k);
    cudaGetSymbolAddress((void**)&pv,    g_v);
    cudaGetSymbolAddress((void**)&pslots,g_slots);
    cudaGetSymbolAddress((void**)&ptmp,  g_tmp);
    cudaGetSymbolAddress((void**)&pq,    g_q);
    cudaGetSymbolAddress((void**)&pdots, g_dots);
    cudaGetSymbolAddress((void**)&pl,    g_lsum);
    cudaGetSymbolAddress((void**)&pupd,  g_upd);
    cudaGetSymbolAddress((void**)&pgx,   g_gx);
    cudaGetSymbolAddress((void**)&pgh,   g_gh);
    cudaGetSymbolAddress((void**)&ph,    g_h);
    cudaGetSymbolAddress((void**)&pt,    g_t);

    const float scale = 1.0f / sqrtf((float)D_DIM);

    // ---- K/V precompute ----
    ln_kernel<<<N_IN, 256>>>(pano, gin, bein, pln);
    gemm_nt_kernel<false><<<dim3(D_DIM / 64, N_IN / 64), 256>>>(
        pln, Wk, bk, nullptr, pk, N_IN, D_DIM, D_DIM, 1.0f);
    gemm_nt_kernel<false><<<dim3(D_DIM / 64, N_IN / 64), 256>>>(
        pln, Wv, bv, nullptr, pv, N_IN, D_DIM, D_DIM, 1.0f);
    copy_kernel<<<(S_SLOTS * D_DIM) / 256, 256>>>(cand, pslots, S_SLOTS * D_DIM);

    for (int it = 0; it < 3; ++it) {
        // q = LN(slots) @ Wq^T + bq
        ln_kernel<<<S_SLOTS, 256>>>(pslots, gsl, besl, ptmp);
        gemm_nt_kernel<false><<<dim3(D_DIM / 64, S_SLOTS / 64), 256>>>(
            ptmp, Wq, bq, nullptr, pq, S_SLOTS, D_DIM, D_DIM, 1.0f);

        // dots = scale * q @ k^T ; softmax (unnormalized, sums in g_lsum)
        gemm_nt_kernel<false><<<dim3(N_IN / 64, S_SLOTS / 64), 256>>>(
            pq, pk, nullptr, nullptr, pdots, S_SLOTS, N_IN, D_DIM, scale);
        softmax_kernel<<<S_SLOTS, 256>>>(pdots, pl);

        // updates = (p @ v) / lsum
        gemm_nn_kernel<<<dim3(D_DIM / 64, S_SLOTS / 64), 256>>>(
            pdots, pv, pupd, S_SLOTS, D_DIM, N_IN);
        rowscale_kernel<<<(S_SLOTS * D_DIM) / 256, 256>>>(pupd, pl);

        // GRU cell
        gemm_nt_kernel<false><<<dim3(D3 / 64, S_SLOTS / 64), 256>>>(
            pupd, Wih, bih, nullptr, pgx, S_SLOTS, D3, D_DIM, 1.0f);
        gemm_nt_kernel<false><<<dim3(D3 / 64, S_SLOTS / 64), 256>>>(
            pslots, Whh, bhh, nullptr, pgh, S_SLOTS, D3, D_DIM, 1.0f);
        gru_kernel<<<(S_SLOTS * D_DIM) / 256, 256>>>(pgx, pgh, pslots, ph);

        // slots = h + relu(LN(h) @ W1^T + b1) @ W2^T + b2
        ln_kernel<<<S_SLOTS, 256>>>(ph, gff, beff, ptmp);
        gemm_nt_kernel<true><<<dim3(D_DIM / 64, S_SLOTS / 64), 256>>>(
            ptmp, W1, b1, nullptr, pt, S_SLOTS, D_DIM, D_DIM, 1.0f);
        float* outp = (it == 2) ? (float*)d_out : pslots;
        gemm_nt_kernel<false><<<dim3(D_DIM / 64, S_SLOTS / 64), 256>>>(
            pt, W2, b2, ph, outp, S_SLOTS, D_DIM, D_DIM, 1.0f);
    }
}

// round 3
// speedup vs baseline: 4.1091x; 4.1091x over previous
#include <cuda_runtime.h>
#include <math.h>
#include <stdint.h>

// ---------------- problem constants ----------------
#define S_SLOTS 4096
#define N_IN    16384
#define D_DIM   768
#define D3      2304

#define BM 128
#define BN 128
#define BK 32
#define PAD 36                       // floats per smem row (conflict-free frag loads)
#define TILE_F (128 * PAD)           // floats per tile
#define GEMM_SMEM (4 * TILE_F * 4)   // 2 stages * (A+B) * 4 bytes = 73728

// ---------------- scratch (device globals) ----------------
__device__ float g_pano_ln[N_IN * D_DIM];
__device__ float g_k      [N_IN * D_DIM];
__device__ float g_v      [N_IN * D_DIM];
__device__ float g_vT     [D_DIM * N_IN];
__device__ float g_slots  [S_SLOTS * D_DIM];
__device__ float g_tmp    [S_SLOTS * D_DIM];
__device__ float g_q      [S_SLOTS * D_DIM];
__device__ float g_dots   [(size_t)S_SLOTS * N_IN];
__device__ float g_lsum   [S_SLOTS];
__device__ float g_upd    [S_SLOTS * D_DIM];
__device__ float g_gx     [S_SLOTS * D3];
__device__ float g_gh     [S_SLOTS * D3];
__device__ float g_h      [S_SLOTS * D_DIM];
__device__ float g_t      [S_SLOTS * D_DIM];
// tf32-rounded weight copies
__device__ float g_Wq [D_DIM * D_DIM];
__device__ float g_Wk [D_DIM * D_DIM];
__device__ float g_Wv [D_DIM * D_DIM];
__device__ float g_W1 [D_DIM * D_DIM];
__device__ float g_W2 [D_DIM * D_DIM];
__device__ float g_Wih[D3 * D_DIM];
__device__ float g_Whh[D3 * D_DIM];

// ---------------- PTX helpers ----------------
__device__ __forceinline__ uint32_t s2u(const void* p) {
    uint32_t a;
    asm("{ .reg .u64 t; cvta.to.shared.u64 t, %1; cvt.u32.u64 %0, t; }" : "=r"(a) : "l"(p));
    return a;
}

__device__ __forceinline__ float rna_tf32(float x) {
    uint32_t u;
    asm("cvt.rna.tf32.f32 %0, %1;" : "=r"(u) : "f"(x));
    return __uint_as_float(u);
}

__device__ __forceinline__ void cp16(uint32_t s, const void* g) {
    asm volatile("cp.async.cg.shared.global [%0], [%1], 16;" :: "r"(s), "l"(g) : "memory");
}

__device__ __forceinline__ void mma_tf32(float* c, uint32_t a0, uint32_t a1,
                                         uint32_t a2, uint32_t a3,
                                         uint32_t b0, uint32_t b1) {
    asm volatile(
        "mma.sync.aligned.m16n8k8.row.col.f32.tf32.tf32.f32 "
        "{%0,%1,%2,%3}, {%4,%5,%6,%7}, {%8,%9}, {%0,%1,%2,%3};"
        : "+f"(c[0]), "+f"(c[1]), "+f"(c[2]), "+f"(c[3])
        : "r"(a0), "r"(a1), "r"(a2), "r"(a3), "r"(b0), "r"(b1));
}

// ---------------- tensor-core tf32 NT GEMM ----------------
// C[M,N] = alpha * A[M,K] @ B[N,K]^T  (+bias[j]) (/rowdiv[i]) (ReLU) (+add[i,j]) (rna)
// M%128==0, N%128==0, K%32==0. ldc = NC.
__global__ void __launch_bounds__(256, 2) gemm_tc(
    const float* __restrict__ A, const float* __restrict__ B, float* __restrict__ C,
    int K, int NC, float alpha,
    const float* __restrict__ bias, const float* __restrict__ rowdiv,
    const float* __restrict__ addsrc, int relu, int dorna)
{
    extern __shared__ float sm[];
    float* As = sm;                 // [2][128][PAD]
    float* Bs = sm + 2 * TILE_F;    // [2][128][PAD]

    int tid = threadIdx.x, lane = tid & 31, wid = tid >> 5;
    int wm = wid & 1, wn = wid >> 1;          // 2 x 4 warp grid
    int m0 = blockIdx.y * BM, n0 = blockIdx.x * BN;
    int KT = K / BK;

    int lr = tid >> 3;          // 0..31
    int lc = (tid & 7) * 4;     // 0,4,...,28
    const float* Ag = A + (size_t)(m0 + lr) * K + lc;
    const float* Bg = B + (size_t)(n0 + lr) * K + lc;
    uint32_t as_u = s2u(As), bs_u = s2u(Bs);

    float acc[4][4][4];
    #pragma unroll
    for (int i = 0; i < 4; i++)
        #pragma unroll
        for (int j = 0; j < 4; j++)
            #pragma unroll
            for (int q = 0; q < 4; q++) acc[i][j][q] = 0.0f;

    // prologue: stages 0 and 1
    #pragma unroll
    for (int p = 0; p < 2; p++) {
        #pragma unroll
        for (int i = 0; i < 4; i++) {
            uint32_t soff = (uint32_t)(p * TILE_F + (lr + i * 32) * PAD + lc) * 4u;
            cp16(as_u + soff, Ag + (size_t)i * 32 * K + (size_t)p * BK);
            cp16(bs_u + soff, Bg + (size_t)i * 32 * K + (size_t)p * BK);
        }
        asm volatile("cp.async.commit_group;" ::: "memory");
    }

    for (int kt = 0; kt < KT; kt++) {
        asm volatile("cp.async.wait_group 1;" ::: "memory");
        __syncthreads();
        int st = kt & 1;
        const float* aw = As + st * TILE_F + wm * 64 * PAD;
        const float* bw = Bs + st * TILE_F + wn * 32 * PAD;

        #pragma unroll
        for (int ks = 0; ks < 4; ks++) {
            int k = ks * 8 + (lane & 3);
            int g4 = lane >> 2;
            uint32_t bf[4][2];
            #pragma unroll
            for (int nf = 0; nf < 4; nf++) {
                const float* bp = bw + (nf * 8 + g4) * PAD + k;
                bf[nf][0] = __float_as_uint(bp[0]);
                bf[nf][1] = __float_as_uint(bp[4]);
            }
            #pragma unroll
            for (int mf = 0; mf < 4; mf++) {
                const float* ap = aw + (mf * 16 + g4) * PAD + k;
                uint32_t a0 = __float_as_uint(ap[0]);
                uint32_t a1 = __float_as_uint(ap[8 * PAD]);
                uint32_t a2 = __float_as_uint(ap[4]);
                uint32_t a3 = __float_as_uint(ap[8 * PAD + 4]);
                #pragma unroll
                for (int nf = 0; nf < 4; nf++)
                    mma_tf32(acc[mf][nf], a0, a1, a2, a3, bf[nf][0], bf[nf][1]);
            }
        }
        __syncthreads();
        if (kt + 2 < KT) {
            #pragma unroll
            for (int i = 0; i < 4; i++) {
                uint32_t soff = (uint32_t)(st * TILE_F + (lr + i * 32) * PAD + lc) * 4u;
                cp16(as_u + soff, Ag + (size_t)i * 32 * K + (size_t)(kt + 2) * BK);
                cp16(bs_u + soff, Bg + (size_t)i * 32 * K + (size_t)(kt + 2) * BK);
            }
        }
        asm volatile("cp.async.commit_group;" ::: "memory");
    }

    // -------- epilogue --------
    int g4 = lane >> 2;
    int c2 = 2 * (lane & 3);
    int rbase = m0 + wm * 64 + g4;
    #pragma unroll
    for (int mf = 0; mf < 4; mf++) {
        int r1 = rbase + mf * 16;
        int r2 = r1 + 8;
        float inv1 = 1.0f, inv2 = 1.0f;
        if (rowdiv) { inv1 = 1.0f / rowdiv[r1]; inv2 = 1.0f / rowdiv[r2]; }
        #pragma unroll
        for (int nf = 0; nf < 4; nf++) {
            int col = n0 + wn * 32 + nf * 8 + c2;
            float b0 = 0.f, b1 = 0.f;
            if (bias) { b0 = bias[col]; b1 = bias[col + 1]; }
            float v00 = acc[mf][nf][0] * alpha + b0;
            float v01 = acc[mf][nf][1] * alpha + b1;
            float v10 = acc[mf][nf][2] * alpha + b0;
            float v11 = acc[mf][nf][3] * alpha + b1;
            v00 *= inv1; v01 *= inv1; v10 *= inv2; v11 *= inv2;
            if (relu) {
                v00 = fmaxf(v00, 0.f); v01 = fmaxf(v01, 0.f);
                v10 = fmaxf(v10, 0.f); v11 = fmaxf(v11, 0.f);
            }
            if (addsrc) {
                const float* s1 = addsrc + (size_t)r1 * NC + col;
                const float* s2 = addsrc + (size_t)r2 * NC + col;
                v00 += s1[0]; v01 += s1[1]; v10 += s2[0]; v11 += s2[1];
            }
            if (dorna) {
                v00 = rna_tf32(v00); v01 = rna_tf32(v01);
                v10 = rna_tf32(v10); v11 = rna_tf32(v11);
            }
            *(float2*)(C + (size_t)r1 * NC + col) = make_float2(v00, v01);
            *(float2*)(C + (size_t)r2 * NC + col) = make_float2(v10, v11);
        }
    }
}

// ---------------- reductions ----------------
__device__ __forceinline__ float blk_sum(float v, float* sm) {
    #pragma unroll
    for (int o = 16; o; o >>= 1) v += __shfl_xor_sync(0xffffffffu, v, o);
    int w = threadIdx.x >> 5;
    if ((threadIdx.x & 31) == 0) sm[w] = v;
    __syncthreads();
    if (threadIdx.x < 8) {
        float x = sm[threadIdx.x];
        #pragma unroll
        for (int o = 4; o; o >>= 1) x += __shfl_xor_sync(0xffu, x, o);
        if (threadIdx.x == 0) sm[0] = x;
    }
    __syncthreads();
    float r = sm[0];
    __syncthreads();
    return r;
}

__device__ __forceinline__ float blk_max(float v, float* sm) {
    #pragma unroll
    for (int o = 16; o; o >>= 1) v = fmaxf(v, __shfl_xor_sync(0xffffffffu, v, o));
    int w = threadIdx.x >> 5;
    if ((threadIdx.x & 31) == 0) sm[w] = v;
    __syncthreads();
    if (threadIdx.x < 8) {
        float x = sm[threadIdx.x];
        #pragma unroll
        for (int o = 4; o; o >>= 1) x = fmaxf(x, __shfl_xor_sync(0xffu, x, o));
        if (threadIdx.x == 0) sm[0] = x;
    }
    __syncthreads();
    float r = sm[0];
    __syncthreads();
    return r;
}

// ---------------- elementwise kernels ----------------
__global__ void copy_rna_kernel(const float* __restrict__ in, float* __restrict__ out, int n) {
    int i = blockIdx.x * 256 + threadIdx.x;
    if (i < n) out[i] = rna_tf32(in[i]);
}

__global__ void __launch_bounds__(256) ln_rna_kernel(
    const float* __restrict__ x, const float* __restrict__ g,
    const float* __restrict__ be, float* __restrict__ y)
{
    __shared__ float sm[8];
    int row = blockIdx.x;
    const float* xr = x + (size_t)row * D_DIM;
    int t = threadIdx.x;
    float v0 = xr[t], v1 = xr[t + 256], v2 = xr[t + 512];
    float s = blk_sum(v0 + v1 + v2, sm);
    float mean = s * (1.0f / 768.0f);
    float d0 = v0 - mean, d1 = v1 - mean, d2 = v2 - mean;
    float ss = blk_sum(d0 * d0 + d1 * d1 + d2 * d2, sm);
    float inv = rsqrtf(ss * (1.0f / 768.0f) + 1e-5f);
    float* yr = y + (size_t)row * D_DIM;
    yr[t]       = rna_tf32(d0 * inv * g[t]       + be[t]);
    yr[t + 256] = rna_tf32(d1 * inv * g[t + 256] + be[t + 256]);
    yr[t + 512] = rna_tf32(d2 * inv * g[t + 512] + be[t + 512]);
}

__global__ void __launch_bounds__(256) softmax_kernel(
    float* __restrict__ dots, float* __restrict__ lsum)
{
    __shared__ float sm[8];
    int row = blockIdx.x;
    float4* p = (float4*)(dots + (size_t)row * N_IN);
    float4 buf[16];
    float m = -1e30f;
    #pragma unroll
    for (int i = 0; i < 16; i++) {
        buf[i] = p[threadIdx.x + i * 256];
        m = fmaxf(m, fmaxf(fmaxf(buf[i].x, buf[i].y), fmaxf(buf[i].z, buf[i].w)));
    }
    m = blk_max(m, sm);
    float s = 0.0f;
    #pragma unroll
    for (int i = 0; i < 16; i++) {
        float4 e;
        e.x = rna_tf32(expf(buf[i].x - m)); e.y = rna_tf32(expf(buf[i].y - m));
        e.z = rna_tf32(expf(buf[i].z - m)); e.w = rna_tf32(expf(buf[i].w - m));
        s += (e.x + e.y) + (e.z + e.w);
        p[threadIdx.x + i * 256] = e;
    }
    s = blk_sum(s, sm);
    if (threadIdx.x == 0) lsum[row] = s;
}

__global__ void transpose_rna(const float* __restrict__ in, float* __restrict__ out) {
    __shared__ float t[32][33];
    int c0 = blockIdx.x * 32, r0 = blockIdx.y * 32;
    for (int i = threadIdx.y; i < 32; i += 8)
        t[i][threadIdx.x] = in[(size_t)(r0 + i) * D_DIM + c0 + threadIdx.x];
    __syncthreads();
    for (int i = threadIdx.y; i < 32; i += 8)
        out[(size_t)(c0 + i) * N_IN + r0 + threadIdx.x] = rna_tf32(t[threadIdx.x][i]);
}

__global__ void gru_kernel(const float* __restrict__ gx, const float* __restrict__ gh,
                           const float* __restrict__ sp, float* __restrict__ h)
{
    int idx = blockIdx.x * 256 + threadIdx.x;
    int i = idx / D_DIM, d = idx - i * D_DIM;
    size_t b3 = (size_t)i * D3;
    float xr = gx[b3 + d], xz = gx[b3 + D_DIM + d], xn = gx[b3 + 2 * D_DIM + d];
    float hr = gh[b3 + d], hz = gh[b3 + D_DIM + d], hn = gh[b3 + 2 * D_DIM + d];
    float r = 1.0f / (1.0f + expf(-(xr + hr)));
    float z = 1.0f / (1.0f + expf(-(xz + hz)));
    float n = tanhf(xn + r * hn);
    h[idx] = (1.0f - z) * n + z * sp[idx];
}

// ---------------- host launch ----------------
static void launch_gemm(const float* A, const float* B, float* C,
                        int M, int N, int K, float alpha,
                        const float* bias, const float* rowdiv, const float* addsrc,
                        int relu, int dorna)
{
    dim3 g(N / BN, M / BM);
    gemm_tc<<<g, 256, GEMM_SMEM>>>(A, B, C, K, N, alpha, bias, rowdiv, addsrc, relu, dorna);
}

extern "C" void kernel_launch(void* const* d_in, const int* in_sizes, int n_in,
                              void* d_out, int out_size)
{
    (void)in_sizes; (void)n_in; (void)out_size;
    const float* cand = (const float*)d_in[0];
    const float* pano = (const float*)d_in[1];
    const float* Wq   = (const float*)d_in[2];
    const float* bq   = (const float*)d_in[3];
    const float* Wk   = (const float*)d_in[4];
    const float* bk   = (const float*)d_in[5];
    const float* Wv   = (const float*)d_in[6];
    const float* bv   = (const float*)d_in[7];
    const float* Wih  = (const float*)d_in[8];
    const float* bih  = (const float*)d_in[9];
    const float* Whh  = (const float*)d_in[10];
    const float* bhh  = (const float*)d_in[11];
    const float* W1   = (const float*)d_in[12];
    const float* b1   = (const float*)d_in[13];
    const float* W2   = (const float*)d_in[14];
    const float* b2   = (const float*)d_in[15];
    const float* gin  = (const float*)d_in[16];
    const float* bein = (const float*)d_in[17];
    const float* gsl  = (const float*)d_in[18];
    const float* besl = (const float*)d_in[19];
    const float* gff  = (const float*)d_in[20];
    const float* beff = (const float*)d_in[21];

    cudaFuncSetAttribute(gemm_tc, cudaFuncAttributeMaxDynamicSharedMemorySize, GEMM_SMEM);

    float *pln, *pk, *pv, *pvT, *pslots, *ptmp, *pq, *pdots, *pl, *pupd, *pgx, *pgh, *ph, *pt;
    float *wq, *wk, *wv, *w1, *w2, *wih, *whh;
    cudaGetSymbolAddress((void**)&pln,   g_pano_ln);
    cudaGetSymbolAddress((void**)&pk,    g_k);
    cudaGetSymbolAddress((void**)&pv,    g_v);
    cudaGetSymbolAddress((void**)&pvT,   g_vT);
    cudaGetSymbolAddress((void**)&pslots,g_slots);
    cudaGetSymbolAddress((void**)&ptmp,  g_tmp);
    cudaGetSymbolAddress((void**)&pq,    g_q);
    cudaGetSymbolAddress((void**)&pdots, g_dots);
    cudaGetSymbolAddress((void**)&pl,    g_lsum);
    cudaGetSymbolAddress((void**)&pupd,  g_upd);
    cudaGetSymbolAddress((void**)&pgx,   g_gx);
    cudaGetSymbolAddress((void**)&pgh,   g_gh);
    cudaGetSymbolAddress((void**)&ph,    g_h);
    cudaGetSymbolAddress((void**)&pt,    g_t);
    cudaGetSymbolAddress((void**)&wq,    g_Wq);
    cudaGetSymbolAddress((void**)&wk,    g_Wk);
    cudaGetSymbolAddress((void**)&wv,    g_Wv);
    cudaGetSymbolAddress((void**)&w1,    g_W1);
    cudaGetSymbolAddress((void**)&w2,    g_W2);
    cudaGetSymbolAddress((void**)&wih,   g_Wih);
    cudaGetSymbolAddress((void**)&whh,   g_Whh);

    const float scale = 1.0f / sqrtf((float)D_DIM);
    const int DD = D_DIM * D_DIM, D3D = D3 * D_DIM;

    // tf32-round the weights once per launch
    copy_rna_kernel<<<(DD + 255) / 256, 256>>>(Wq, wq, DD);
    copy_rna_kernel<<<(DD + 255) / 256, 256>>>(Wk, wk, DD);
    copy_rna_kernel<<<(DD + 255) / 256, 256>>>(Wv, wv, DD);
    copy_rna_kernel<<<(DD + 255) / 256, 256>>>(W1, w1, DD);
    copy_rna_kernel<<<(DD + 255) / 256, 256>>>(W2, w2, DD);
    copy_rna_kernel<<<(D3D + 255) / 256, 256>>>(Wih, wih, D3D);
    copy_rna_kernel<<<(D3D + 255) / 256, 256>>>(Whh, whh, D3D);

    // K/V precompute
    ln_rna_kernel<<<N_IN, 256>>>(pano, gin, bein, pln);
    launch_gemm(pln, wk, pk, N_IN, D_DIM, D_DIM, 1.0f, bk, 0, 0, 0, 1);
    launch_gemm(pln, wv, pv, N_IN, D_DIM, D_DIM, 1.0f, bv, 0, 0, 0, 0);
    transpose_rna<<<dim3(D_DIM / 32, N_IN / 32), dim3(32, 8)>>>(pv, pvT);
    copy_rna_kernel<<<(S_SLOTS * D_DIM) / 256, 256>>>(cand, pslots, S_SLOTS * D_DIM);

    for (int it = 0; it < 3; ++it) {
        // q = LN(slots) @ Wq^T + bq
        ln_rna_kernel<<<S_SLOTS, 256>>>(pslots, gsl, besl, ptmp);
        launch_gemm(ptmp, wq, pq, S_SLOTS, D_DIM, D_DIM, 1.0f, bq, 0, 0, 0, 1);

        // dots = scale * q @ k^T ; softmax (unnormalized exp, row sums -> lsum)
        launch_gemm(pq, pk, pdots, S_SLOTS, N_IN, D_DIM, scale, 0, 0, 0, 0, 0);
        softmax_kernel<<<S_SLOTS, 256>>>(pdots, pl);

        // updates = (P @ v) / lsum   (v^T pre-transposed)
        launch_gemm(pdots, pvT, pupd, S_SLOTS, D_DIM, N_IN, 1.0f, 0, pl, 0, 0, 1);

        // GRU gates
        launch_gemm(pupd,   wih, pgx, S_SLOTS, D3, D_DIM, 1.0f, bih, 0, 0, 0, 0);
        launch_gemm(pslots, whh, pgh, S_SLOTS, D3, D_DIM, 1.0f, bhh, 0, 0, 0, 0);
        gru_kernel<<<(S_SLOTS * D_DIM) / 256, 256>>>(pgx, pgh, pslots, ph);

        // slots = h + relu(LN(h) @ W1^T + b1) @ W2^T + b2
        ln_rna_kernel<<<S_SLOTS, 256>>>(ph, gff, beff, ptmp);
        launch_gemm(ptmp, w1, pt, S_SLOTS, D_DIM, D_DIM, 1.0f, b1, 0, 0, 1, 1);
        float* outp = (it == 2) ? (float*)d_out : pslots;
        launch_gemm(pt, w2, outp, S_SLOTS, D_DIM, D_DIM, 1.0f, b2, 0, ph, 0, (it == 2) ? 0 : 1);
    }
}

// round 4
// speedup vs baseline: 5.8131x; 1.4147x over previous
#include <cuda_runtime.h>
#include <cuda_fp16.h>
#include <math.h>
#include <stdint.h>

// ---------------- problem constants ----------------
#define S_SLOTS 4096
#define N_IN    16384
#define D_DIM   768
#define D3      2304

#define BM 128
#define BN 128
#define BKH 32                  // halves per k-stage
#define PADH 40                 // halves per smem row (conflict-free frags)
#define TILE_H (128 * PADH)     // halves per tile
#define STAGES 4
#define GEMM_SMEM (STAGES * 2 * TILE_H * 2)   // 81920 bytes

// ---------------- scratch (device globals) ----------------
// fp32
__device__ float g_slots [S_SLOTS * D_DIM];
__device__ float g_dots  [(size_t)S_SLOTS * N_IN];
__device__ float g_lsum  [S_SLOTS];
__device__ float g_gx    [S_SLOTS * D3];
__device__ float g_gh    [S_SLOTS * D3];
__device__ float g_h     [S_SLOTS * D_DIM];
// fp16 operands
__device__ __half g_pln_h  [N_IN * D_DIM];
__device__ __half g_k_h    [N_IN * D_DIM];
__device__ __half g_v_h    [N_IN * D_DIM];
__device__ __half g_vT_h   [D_DIM * N_IN];
__device__ __half g_slots_h[S_SLOTS * D_DIM];
__device__ __half g_tmp_h  [S_SLOTS * D_DIM];
__device__ __half g_q_h    [S_SLOTS * D_DIM];
__device__ __half g_p_h    [(size_t)S_SLOTS * N_IN];
__device__ __half g_upd_h  [S_SLOTS * D_DIM];
__device__ __half g_t_h    [S_SLOTS * D_DIM];
// fp16 weights
__device__ __half g_Wq [D_DIM * D_DIM];
__device__ __half g_Wk [D_DIM * D_DIM];
__device__ __half g_Wv [D_DIM * D_DIM];
__device__ __half g_W1 [D_DIM * D_DIM];
__device__ __half g_W2 [D_DIM * D_DIM];
__device__ __half g_Wih[D3 * D_DIM];
__device__ __half g_Whh[D3 * D_DIM];

// ---------------- PTX helpers ----------------
__device__ __forceinline__ uint32_t s2u(const void* p) {
    uint32_t a;
    asm("{ .reg .u64 t; cvta.to.shared.u64 t, %1; cvt.u32.u64 %0, t; }" : "=r"(a) : "l"(p));
    return a;
}

__device__ __forceinline__ void cp16(uint32_t s, const void* g) {
    asm volatile("cp.async.cg.shared.global [%0], [%1], 16;" :: "r"(s), "l"(g) : "memory");
}

__device__ __forceinline__ void mma_f16(float* c, uint32_t a0, uint32_t a1,
                                        uint32_t a2, uint32_t a3,
                                        uint32_t b0, uint32_t b1) {
    asm volatile(
        "mma.sync.aligned.m16n8k16.row.col.f32.f16.f16.f32 "
        "{%0,%1,%2,%3}, {%4,%5,%6,%7}, {%8,%9}, {%0,%1,%2,%3};"
        : "+f"(c[0]), "+f"(c[1]), "+f"(c[2]), "+f"(c[3])
        : "r"(a0), "r"(a1), "r"(a2), "r"(a3), "r"(b0), "r"(b1));
}

// ---------------- fp16 tensor-core NT GEMM ----------------
// acc = alpha * A[M,K] @ B[N,K]^T (+bias[j]) (/rowdiv[i]) (ReLU) (+add[i,j])
// writes C32 (fp32) and/or C16 (fp16). M%128==0, N%128==0, K%32==0. ldc = NC.
__global__ void __launch_bounds__(256, 2) gemm_h(
    const __half* __restrict__ A, const __half* __restrict__ B,
    float* __restrict__ C32, __half* __restrict__ C16,
    int K, int NC, float alpha,
    const float* __restrict__ bias, const float* __restrict__ rowdiv,
    const float* __restrict__ addsrc, int relu)
{
    extern __shared__ __half smh[];
    __half* As = smh;                     // [STAGES][128][PADH]
    __half* Bs = smh + STAGES * TILE_H;

    int tid = threadIdx.x, lane = tid & 31, wid = tid >> 5;
    int wm = wid & 1, wn = wid >> 1;      // 2 x 4 warp grid
    int m0 = blockIdx.y * BM, n0 = blockIdx.x * BN;
    int KT = K / BKH;

    int lr = tid >> 2;          // 0..63
    int cch = tid & 3;          // 16B chunk (8 halves) in a 32-half row slice
    const __half* Ag = A + (size_t)(m0 + lr) * K + cch * 8;
    const __half* Bg = B + (size_t)(n0 + lr) * K + cch * 8;
    uint32_t as_u = s2u(As), bs_u = s2u(Bs);

    float acc[4][4][4];
    #pragma unroll
    for (int i = 0; i < 4; i++)
        #pragma unroll
        for (int j = 0; j < 4; j++)
            #pragma unroll
            for (int q = 0; q < 4; q++) acc[i][j][q] = 0.0f;

    // prologue: stages 0..2
    #pragma unroll
    for (int p = 0; p < 3; p++) {
        #pragma unroll
        for (int i = 0; i < 2; i++) {
            uint32_t soff = (uint32_t)(p * TILE_H + (lr + i * 64) * PADH) * 2u + cch * 16u;
            cp16(as_u + soff, Ag + (size_t)i * 64 * K + (size_t)p * BKH);
            cp16(bs_u + soff, Bg + (size_t)i * 64 * K + (size_t)p * BKH);
        }
        asm volatile("cp.async.commit_group;" ::: "memory");
    }

    int g4 = lane >> 2, q4 = lane & 3;

    for (int kt = 0; kt < KT; kt++) {
        asm volatile("cp.async.wait_group 2;" ::: "memory");
        __syncthreads();
        int st = kt & (STAGES - 1);
        if (kt + 3 < KT) {
            int d = (kt + 3) & (STAGES - 1);
            #pragma unroll
            for (int i = 0; i < 2; i++) {
                uint32_t soff = (uint32_t)(d * TILE_H + (lr + i * 64) * PADH) * 2u + cch * 16u;
                cp16(as_u + soff, Ag + (size_t)i * 64 * K + (size_t)(kt + 3) * BKH);
                cp16(bs_u + soff, Bg + (size_t)i * 64 * K + (size_t)(kt + 3) * BKH);
            }
        }
        asm volatile("cp.async.commit_group;" ::: "memory");

        const __half* aw = As + st * TILE_H + (wm * 64 + g4) * PADH + q4 * 2;
        const __half* bw = Bs + st * TILE_H + (wn * 32 + g4) * PADH + q4 * 2;

        #pragma unroll
        for (int ks = 0; ks < 2; ks++) {         // two k16 steps per 32-half stage
            int kb = ks * 16;
            uint32_t bf[4][2];
            #pragma unroll
            for (int nf = 0; nf < 4; nf++) {
                const __half* bp = bw + nf * 8 * PADH + kb;
                bf[nf][0] = *(const uint32_t*)bp;
                bf[nf][1] = *(const uint32_t*)(bp + 8);
            }
            #pragma unroll
            for (int mf = 0; mf < 4; mf++) {
                const __half* ap = aw + mf * 16 * PADH + kb;
                uint32_t a0 = *(const uint32_t*)ap;
                uint32_t a1 = *(const uint32_t*)(ap + 8 * PADH);
                uint32_t a2 = *(const uint32_t*)(ap + 8);
                uint32_t a3 = *(const uint32_t*)(ap + 8 * PADH + 8);
                #pragma unroll
                for (int nf = 0; nf < 4; nf++)
                    mma_f16(acc[mf][nf], a0, a1, a2, a3, bf[nf][0], bf[nf][1]);
            }
        }
    }

    // -------- epilogue --------
    int c2 = 2 * q4;
    int rbase = m0 + wm * 64 + g4;
    #pragma unroll
    for (int mf = 0; mf < 4; mf++) {
        int r1 = rbase + mf * 16;
        int r2 = r1 + 8;
        float inv1 = 1.0f, inv2 = 1.0f;
        if (rowdiv) { inv1 = 1.0f / rowdiv[r1]; inv2 = 1.0f / rowdiv[r2]; }
        #pragma unroll
        for (int nf = 0; nf < 4; nf++) {
            int col = n0 + wn * 32 + nf * 8 + c2;
            float b0 = 0.f, b1 = 0.f;
            if (bias) { b0 = bias[col]; b1 = bias[col + 1]; }
            float v00 = acc[mf][nf][0] * alpha + b0;
            float v01 = acc[mf][nf][1] * alpha + b1;
            float v10 = acc[mf][nf][2] * alpha + b0;
            float v11 = acc[mf][nf][3] * alpha + b1;
            v00 *= inv1; v01 *= inv1; v10 *= inv2; v11 *= inv2;
            if (relu) {
                v00 = fmaxf(v00, 0.f); v01 = fmaxf(v01, 0.f);
                v10 = fmaxf(v10, 0.f); v11 = fmaxf(v11, 0.f);
            }
            if (addsrc) {
                const float* s1 = addsrc + (size_t)r1 * NC + col;
                const float* s2 = addsrc + (size_t)r2 * NC + col;
                v00 += s1[0]; v01 += s1[1]; v10 += s2[0]; v11 += s2[1];
            }
            if (C32) {
                *(float2*)(C32 + (size_t)r1 * NC + col) = make_float2(v00, v01);
                *(float2*)(C32 + (size_t)r2 * NC + col) = make_float2(v10, v11);
            }
            if (C16) {
                *(__half2*)(C16 + (size_t)r1 * NC + col) = __floats2half2_rn(v00, v01);
                *(__half2*)(C16 + (size_t)r2 * NC + col) = __floats2half2_rn(v10, v11);
            }
        }
    }
}

// ---------------- reductions ----------------
__device__ __forceinline__ float blk_sum(float v, float* sm) {
    #pragma unroll
    for (int o = 16; o; o >>= 1) v += __shfl_xor_sync(0xffffffffu, v, o);
    int w = threadIdx.x >> 5;
    if ((threadIdx.x & 31) == 0) sm[w] = v;
    __syncthreads();
    if (threadIdx.x < 8) {
        float x = sm[threadIdx.x];
        #pragma unroll
        for (int o = 4; o; o >>= 1) x += __shfl_xor_sync(0xffu, x, o);
        if (threadIdx.x == 0) sm[0] = x;
    }
    __syncthreads();
    float r = sm[0];
    __syncthreads();
    return r;
}

__device__ __forceinline__ float blk_max(float v, float* sm) {
    #pragma unroll
    for (int o = 16; o; o >>= 1) v = fmaxf(v, __shfl_xor_sync(0xffffffffu, v, o));
    int w = threadIdx.x >> 5;
    if ((threadIdx.x & 31) == 0) sm[w] = v;
    __syncthreads();
    if (threadIdx.x < 8) {
        float x = sm[threadIdx.x];
        #pragma unroll
        for (int o = 4; o; o >>= 1) x = fmaxf(x, __shfl_xor_sync(0xffu, x, o));
        if (threadIdx.x == 0) sm[0] = x;
    }
    __syncthreads();
    float r = sm[0];
    __syncthreads();
    return r;
}

// ---------------- elementwise kernels ----------------
__global__ void to_half_kernel(const float* __restrict__ in, __half* __restrict__ out, int n) {
    int i = blockIdx.x * 256 + threadIdx.x;
    if (i < n) out[i] = __float2half_rn(in[i]);
}

__global__ void copy_both_kernel(const float* __restrict__ in, float* __restrict__ o32,
                                 __half* __restrict__ o16, int n) {
    int i = blockIdx.x * 256 + threadIdx.x;
    if (i < n) { float v = in[i]; o32[i] = v; o16[i] = __float2half_rn(v); }
}

// LayerNorm fp32 -> fp16 (always feeds a GEMM operand)
__global__ void __launch_bounds__(256) ln_h_kernel(
    const float* __restrict__ x, const float* __restrict__ g,
    const float* __restrict__ be, __half* __restrict__ y)
{
    __shared__ float sm[8];
    int row = blockIdx.x;
    const float* xr = x + (size_t)row * D_DIM;
    int t = threadIdx.x;
    float v0 = xr[t], v1 = xr[t + 256], v2 = xr[t + 512];
    float s = blk_sum(v0 + v1 + v2, sm);
    float mean = s * (1.0f / 768.0f);
    float d0 = v0 - mean, d1 = v1 - mean, d2 = v2 - mean;
    float ss = blk_sum(d0 * d0 + d1 * d1 + d2 * d2, sm);
    float inv = rsqrtf(ss * (1.0f / 768.0f) + 1e-5f);
    __half* yr = y + (size_t)row * D_DIM;
    yr[t]       = __float2half_rn(d0 * inv * g[t]       + be[t]);
    yr[t + 256] = __float2half_rn(d1 * inv * g[t + 256] + be[t + 256]);
    yr[t + 512] = __float2half_rn(d2 * inv * g[t + 512] + be[t + 512]);
}

// row max over fp32 dots, exp -> fp16 p, sum of fp16-rounded exps -> lsum
__global__ void __launch_bounds__(256) softmax_kernel(
    const float* __restrict__ dots, __half* __restrict__ p, float* __restrict__ lsum)
{
    __shared__ float sm[8];
    int row = blockIdx.x;
    const float4* dp = (const float4*)(dots + (size_t)row * N_IN);
    float4 buf[16];
    float m = -1e30f;
    #pragma unroll
    for (int i = 0; i < 16; i++) {
        buf[i] = dp[threadIdx.x + i * 256];
        m = fmaxf(m, fmaxf(fmaxf(buf[i].x, buf[i].y), fmaxf(buf[i].z, buf[i].w)));
    }
    m = blk_max(m, sm);
    __half* pr = p + (size_t)row * N_IN;
    float s = 0.0f;
    #pragma unroll
    for (int i = 0; i < 16; i++) {
        __half2 h0 = __floats2half2_rn(expf(buf[i].x - m), expf(buf[i].y - m));
        __half2 h1 = __floats2half2_rn(expf(buf[i].z - m), expf(buf[i].w - m));
        float2 f0 = __half22float2(h0), f1 = __half22float2(h1);
        s += (f0.x + f0.y) + (f1.x + f1.y);
        *(__half2*)(pr + 4 * (threadIdx.x + i * 256))     = h0;
        *(__half2*)(pr + 4 * (threadIdx.x + i * 256) + 2) = h1;
    }
    s = blk_sum(s, sm);
    if (threadIdx.x == 0) lsum[row] = s;
}

// v_h [N_IN, D_DIM] -> vT_h [D_DIM, N_IN]
__global__ void transpose_h(const __half* __restrict__ in, __half* __restrict__ out) {
    __shared__ __half t[32][33];
    int c0 = blockIdx.x * 32, r0 = blockIdx.y * 32;
    for (int i = threadIdx.y; i < 32; i += 8)
        t[i][threadIdx.x] = in[(size_t)(r0 + i) * D_DIM + c0 + threadIdx.x];
    __syncthreads();
    for (int i = threadIdx.y; i < 32; i += 8)
        out[(size_t)(c0 + i) * N_IN + r0 + threadIdx.x] = t[threadIdx.x][i];
}

__global__ void gru_kernel(const float* __restrict__ gx, const float* __restrict__ gh,
                           const float* __restrict__ sp, float* __restrict__ h)
{
    int idx = blockIdx.x * 256 + threadIdx.x;
    int i = idx / D_DIM, d = idx - i * D_DIM;
    size_t b3 = (size_t)i * D3;
    float xr = gx[b3 + d], xz = gx[b3 + D_DIM + d], xn = gx[b3 + 2 * D_DIM + d];
    float hr = gh[b3 + d], hz = gh[b3 + D_DIM + d], hn = gh[b3 + 2 * D_DIM + d];
    float r = 1.0f / (1.0f + expf(-(xr + hr)));
    float z = 1.0f / (1.0f + expf(-(xz + hz)));
    float n = tanhf(xn + r * hn);
    h[idx] = (1.0f - z) * n + z * sp[idx];
}

// ---------------- host launch ----------------
static void launch_gemm(const __half* A, const __half* B, float* C32, __half* C16,
                        int M, int N, int K, float alpha,
                        const float* bias, const float* rowdiv, const float* addsrc,
                        int relu)
{
    dim3 g(N / BN, M / BM);
    gemm_h<<<g, 256, GEMM_SMEM>>>(A, B, C32, C16, K, N, alpha, bias, rowdiv, addsrc, relu);
}

extern "C" void kernel_launch(void* const* d_in, const int* in_sizes, int n_in,
                              void* d_out, int out_size)
{
    (void)in_sizes; (void)n_in; (void)out_size;
    const float* cand = (const float*)d_in[0];
    const float* pano = (const float*)d_in[1];
    const float* Wq   = (const float*)d_in[2];
    const float* bq   = (const float*)d_in[3];
    const float* Wk   = (const float*)d_in[4];
    const float* bk   = (const float*)d_in[5];
    const float* Wv   = (const float*)d_in[6];
    const float* bv   = (const float*)d_in[7];
    const float* Wih  = (const float*)d_in[8];
    const float* bih  = (const float*)d_in[9];
    const float* Whh  = (const float*)d_in[10];
    const float* bhh  = (const float*)d_in[11];
    const float* W1   = (const float*)d_in[12];
    const float* b1   = (const float*)d_in[13];
    const float* W2   = (const float*)d_in[14];
    const float* b2   = (const float*)d_in[15];
    const float* bein = (const float*)d_in[17];
    const float* gin  = (const float*)d_in[16];
    const float* gsl  = (const float*)d_in[18];
    const float* besl = (const float*)d_in[19];
    const float* gff  = (const float*)d_in[20];
    const float* beff = (const float*)d_in[21];

    cudaFuncSetAttribute(gemm_h, cudaFuncAttributeMaxDynamicSharedMemorySize, GEMM_SMEM);

    float *pslots, *pdots, *pl, *pgx, *pgh, *ph;
    __half *pln_h, *pk_h, *pv_h, *pvT_h, *pslots_h, *ptmp_h, *pq_h, *pp_h, *pupd_h, *pt_h;
    __half *wq, *wk, *wv, *w1, *w2, *wih, *whh;
    cudaGetSymbolAddress((void**)&pslots,  g_slots);
    cudaGetSymbolAddress((void**)&pdots,   g_dots);
    cudaGetSymbolAddress((void**)&pl,      g_lsum);
    cudaGetSymbolAddress((void**)&pgx,     g_gx);
    cudaGetSymbolAddress((void**)&pgh,     g_gh);
    cudaGetSymbolAddress((void**)&ph,      g_h);
    cudaGetSymbolAddress((void**)&pln_h,   g_pln_h);
    cudaGetSymbolAddress((void**)&pk_h,    g_k_h);
    cudaGetSymbolAddress((void**)&pv_h,    g_v_h);
    cudaGetSymbolAddress((void**)&pvT_h,   g_vT_h);
    cudaGetSymbolAddress((void**)&pslots_h,g_slots_h);
    cudaGetSymbolAddress((void**)&ptmp_h,  g_tmp_h);
    cudaGetSymbolAddress((void**)&pq_h,    g_q_h);
    cudaGetSymbolAddress((void**)&pp_h,    g_p_h);
    cudaGetSymbolAddress((void**)&pupd_h,  g_upd_h);
    cudaGetSymbolAddress((void**)&pt_h,    g_t_h);
    cudaGetSymbolAddress((void**)&wq,      g_Wq);
    cudaGetSymbolAddress((void**)&wk,      g_Wk);
    cudaGetSymbolAddress((void**)&wv,      g_Wv);
    cudaGetSymbolAddress((void**)&w1,      g_W1);
    cudaGetSymbolAddress((void**)&w2,      g_W2);
    cudaGetSymbolAddress((void**)&wih,     g_Wih);
    cudaGetSymbolAddress((void**)&whh,     g_Whh);

    const float scale = 1.0f / sqrtf((float)D_DIM);
    const int DD = D_DIM * D_DIM, D3D = D3 * D_DIM;

    // fp16 weight copies
    to_half_kernel<<<(DD + 255) / 256, 256>>>(Wq, wq, DD);
    to_half_kernel<<<(DD + 255) / 256, 256>>>(Wk, wk, DD);
    to_half_kernel<<<(DD + 255) / 256, 256>>>(Wv, wv, DD);
    to_half_kernel<<<(DD + 255) / 256, 256>>>(W1, w1, DD);
    to_half_kernel<<<(DD + 255) / 256, 256>>>(W2, w2, DD);
    to_half_kernel<<<(D3D + 255) / 256, 256>>>(Wih, wih, D3D);
    to_half_kernel<<<(D3D + 255) / 256, 256>>>(Whh, whh, D3D);

    // K/V precompute
    ln_h_kernel<<<N_IN, 256>>>(pano, gin, bein, pln_h);
    launch_gemm(pln_h, wk, 0, pk_h, N_IN, D_DIM, D_DIM, 1.0f, bk, 0, 0, 0);
    launch_gemm(pln_h, wv, 0, pv_h, N_IN, D_DIM, D_DIM, 1.0f, bv, 0, 0, 0);
    transpose_h<<<dim3(D_DIM / 32, N_IN / 32), dim3(32, 8)>>>(pv_h, pvT_h);
    copy_both_kernel<<<(S_SLOTS * D_DIM) / 256, 256>>>(cand, pslots, pslots_h, S_SLOTS * D_DIM);

    for (int it = 0; it < 3; ++it) {
        // q = LN(slots) @ Wq^T + bq
        ln_h_kernel<<<S_SLOTS, 256>>>(pslots, gsl, besl, ptmp_h);
        launch_gemm(ptmp_h, wq, 0, pq_h, S_SLOTS, D_DIM, D_DIM, 1.0f, bq, 0, 0, 0);

        // dots = scale * q @ k^T (fp32) ; softmax -> fp16 P, row sums -> lsum
        launch_gemm(pq_h, pk_h, pdots, 0, S_SLOTS, N_IN, D_DIM, scale, 0, 0, 0, 0);
        softmax_kernel<<<S_SLOTS, 256>>>(pdots, pp_h, pl);

        // updates = (P @ v) / lsum
        launch_gemm(pp_h, pvT_h, 0, pupd_h, S_SLOTS, D_DIM, N_IN, 1.0f, 0, pl, 0, 0);

        // GRU gates
        launch_gemm(pupd_h,   wih, pgx, 0, S_SLOTS, D3, D_DIM, 1.0f, bih, 0, 0, 0);
        launch_gemm(pslots_h, whh, pgh, 0, S_SLOTS, D3, D_DIM, 1.0f, bhh, 0, 0, 0);
        gru_kernel<<<(S_SLOTS * D_DIM) / 256, 256>>>(pgx, pgh, pslots, ph);

        // slots = h + relu(LN(h) @ W1^T + b1) @ W2^T + b2
        ln_h_kernel<<<S_SLOTS, 256>>>(ph, gff, beff, ptmp_h);
        launch_gemm(ptmp_h, w1, 0, pt_h, S_SLOTS, D_DIM, D_DIM, 1.0f, b1, 0, 0, 1);
        if (it == 2) {
            launch_gemm(pt_h, w2, (float*)d_out, 0, S_SLOTS, D_DIM, D_DIM, 1.0f, b2, 0, ph, 0);
        } else {
            launch_gemm(pt_h, w2, pslots, pslots_h, S_SLOTS, D_DIM, D_DIM, 1.0f, b2, 0, ph, 0);
        }
    }
}